// round 2
// baseline (speedup 1.0000x reference)
#include <cuda_runtime.h>
#include <math.h>

// Dims
constexpr int DS  = 256;   // S
constexpr int DN  = 768;   // N
constexpr int DCM = 64;    // CM
constexpr int DCZ = 128;   // CZ
constexpr int DH  = 8;     // heads
constexpr int DCH = 32;    // per-head channels
constexpr int DHC = 256;   // H*CH
constexpr int DSN = DS * DN;          // 196608 rows of m
constexpr int DNN = DN * DN;          // 589824 pairs
constexpr int DCOL = DS * DCH;        // 8192 GEMM cols

// Scratch (device globals; no allocations allowed)
__device__ float d_v[DH * DN * DS * DCH];   // [h][j][s][d]
__device__ float d_g[DSN * DHC];            // [s*N+j][hc]
__device__ float d_b[DH * DN * DN];         // [h][i][j]  (logits -> softmax in place)
__device__ float d_o[DH * DN * DS * DCH];   // [h][i][s][d]

// ---------------------------------------------------------------------------
// K1: LN(m) -> v = mln @ Wm^T (scattered to [h][j][s][d]), g = sigmoid(mln @ Wg^T)
// ---------------------------------------------------------------------------
constexpr int K1_WT_STRIDE = 516;
constexpr int K1_SMEM = (64 * K1_WT_STRIDE + 64 * 68 + 64 * 68) * 4;

__global__ void k1_ln_vg(const float* __restrict__ m,
                         const float* __restrict__ nw,
                         const float* __restrict__ nb,
                         const float* __restrict__ Wm,
                         const float* __restrict__ Wg) {
    extern __shared__ float sm1[];
    float* Wt   = sm1;                         // [64][516]
    float* mlnT = sm1 + 64 * K1_WT_STRIDE;     // [64][68]
    float* mraw = mlnT + 64 * 68;              // [64][68]

    const int tid = threadIdx.x;
    const int gr0 = blockIdx.x * 64;

    #pragma unroll
    for (int t = 0; t < 4; t++) {
        int f = tid + t * 256;                 // float4 id 0..1023
        int r = f >> 4;
        int k = (f & 15) << 2;
        float4 v4 = *(const float4*)&m[(size_t)(gr0 + r) * DCM + k];
        *(float4*)&mraw[r * 68 + k] = v4;
    }
    for (int t = 0; t < 128; t++) {
        int idx = tid + t * 256;               // 0..32767
        int o = idx >> 6;                      // 0..511
        int k = idx & 63;
        float val = (o < 256) ? Wm[o * DCM + k] : Wg[(o - 256) * DCM + k];
        Wt[k * K1_WT_STRIDE + o] = val;
    }
    __syncthreads();

    if (tid < 64) {
        float s1 = 0.f, s2 = 0.f;
        #pragma unroll
        for (int k = 0; k < 64; k++) {
            float x = mraw[tid * 68 + k];
            s1 += x; s2 += x * x;
        }
        float mu  = s1 * (1.f / 64.f);
        float var = s2 * (1.f / 64.f) - mu * mu;
        float inv = rsqrtf(var + 1e-5f);
        #pragma unroll
        for (int k = 0; k < 64; k++) {
            float x = mraw[tid * 68 + k];
            mlnT[k * 68 + tid] = (x - mu) * inv * nw[k] + nb[k];
        }
    }
    __syncthreads();

    const int w = tid >> 5;   // warp 0..7 -> rows w*8..w*8+7
    const int l = tid & 31;   // lane -> cols cb*128 + l*4

    float acc[4][8][4];
    #pragma unroll
    for (int cb = 0; cb < 4; cb++)
        #pragma unroll
        for (int i = 0; i < 8; i++)
            #pragma unroll
            for (int j = 0; j < 4; j++) acc[cb][i][j] = 0.f;

    #pragma unroll 4
    for (int k = 0; k < 64; k++) {
        float a[8];
        *(float4*)&a[0] = *(const float4*)&mlnT[k * 68 + w * 8];
        *(float4*)&a[4] = *(const float4*)&mlnT[k * 68 + w * 8 + 4];
        #pragma unroll
        for (int cb = 0; cb < 4; cb++) {
            float4 bv = *(const float4*)&Wt[k * K1_WT_STRIDE + cb * 128 + l * 4];
            float b[4] = {bv.x, bv.y, bv.z, bv.w};
            #pragma unroll
            for (int i = 0; i < 8; i++)
                #pragma unroll
                for (int j = 0; j < 4; j++)
                    acc[cb][i][j] += a[i] * b[j];
        }
    }

    #pragma unroll
    for (int i = 0; i < 8; i++) {
        int rowg = gr0 + w * 8 + i;
        int ss = rowg / DN;
        int jj = rowg % DN;
        #pragma unroll
        for (int cb = 0; cb < 4; cb++) {
            int c = cb * 128 + l * 4;
            if (c < 256) {
                int h = c >> 5, d = c & 31;
                float4 val = make_float4(acc[cb][i][0], acc[cb][i][1],
                                         acc[cb][i][2], acc[cb][i][3]);
                *(float4*)&d_v[((size_t)(h * DN + jj) * DS + ss) * DCH + d] = val;
            } else {
                int cg = c - 256;
                float4 val;
                val.x = 1.f / (1.f + __expf(-acc[cb][i][0]));
                val.y = 1.f / (1.f + __expf(-acc[cb][i][1]));
                val.z = 1.f / (1.f + __expf(-acc[cb][i][2]));
                val.w = 1.f / (1.f + __expf(-acc[cb][i][3]));
                *(float4*)&d_g[(size_t)rowg * DHC + cg] = val;
            }
        }
    }
}

// ---------------------------------------------------------------------------
// K2: LN(z) + b[h][i][j] = dot(zln, Wz[h]) + mask penalty. One warp per pair.
// mask is a bool array uploaded as int32 by the harness -> read as const int*.
// ---------------------------------------------------------------------------
__global__ void k2_ln_bias(const float* __restrict__ z,
                           const int* __restrict__ mask,
                           const float* __restrict__ nw,
                           const float* __restrict__ nb,
                           const float* __restrict__ Wz) {
    int gwarp = (blockIdx.x * blockDim.x + threadIdx.x) >> 5;
    int l = threadIdx.x & 31;
    if (gwarp >= DNN) return;

    const float* zr = z + (size_t)gwarp * DCZ;
    float4 xv = *(const float4*)&zr[l * 4];
    float s1 = xv.x + xv.y + xv.z + xv.w;
    float s2 = xv.x * xv.x + xv.y * xv.y + xv.z * xv.z + xv.w * xv.w;
    #pragma unroll
    for (int off = 16; off; off >>= 1) {
        s1 += __shfl_xor_sync(0xffffffffu, s1, off);
        s2 += __shfl_xor_sync(0xffffffffu, s2, off);
    }
    float mu = s1 * (1.f / 128.f);
    float inv = rsqrtf(s2 * (1.f / 128.f) - mu * mu + 1e-5f);
    float4 wv = *(const float4*)&nw[l * 4];
    float4 bv = *(const float4*)&nb[l * 4];
    float xn0 = (xv.x - mu) * inv * wv.x + bv.x;
    float xn1 = (xv.y - mu) * inv * wv.y + bv.y;
    float xn2 = (xv.z - mu) * inv * wv.z + bv.z;
    float xn3 = (xv.w - mu) * inv * wv.w + bv.w;

    float myb = 0.f;
    #pragma unroll
    for (int h = 0; h < DH; h++) {
        float4 w4 = *(const float4*)&Wz[h * DCZ + l * 4];
        float p = xn0 * w4.x + xn1 * w4.y + xn2 * w4.z + xn3 * w4.w;
        #pragma unroll
        for (int off = 16; off; off >>= 1)
            p += __shfl_xor_sync(0xffffffffu, p, off);
        if (l == h) myb = p;
    }
    if (l < DH) {
        float pen = (mask[gwarp] != 0) ? 0.f : -1e6f;
        d_b[(size_t)l * DNN + gwarp] = myb + pen;
    }
}

// ---------------------------------------------------------------------------
// K3: softmax over j (768) per (h,i) row. In place on d_b. Block = 256 thr/row.
// ---------------------------------------------------------------------------
__global__ void k3_softmax() {
    __shared__ float sd[256];
    float* p = d_b + (size_t)blockIdx.x * DN;
    int tid = threadIdx.x;
    float x0 = p[tid], x1 = p[tid + 256], x2 = p[tid + 512];
    float mx = fmaxf(x0, fmaxf(x1, x2));
    sd[tid] = mx; __syncthreads();
    #pragma unroll
    for (int s = 128; s; s >>= 1) {
        if (tid < s) sd[tid] = fmaxf(sd[tid], sd[tid + s]);
        __syncthreads();
    }
    float bm = sd[0]; __syncthreads();
    float e0 = __expf(x0 - bm), e1 = __expf(x1 - bm), e2 = __expf(x2 - bm);
    sd[tid] = e0 + e1 + e2; __syncthreads();
    #pragma unroll
    for (int s = 128; s; s >>= 1) {
        if (tid < s) sd[tid] += sd[tid + s];
        __syncthreads();
    }
    float invs = 1.f / sd[0];
    p[tid] = e0 * invs; p[tid + 256] = e1 * invs; p[tid + 512] = e2 * invs;
}

// ---------------------------------------------------------------------------
// K4: per-head SGEMM. C[h](768 x 8192) = W[h](768 x 768) @ V[h](768 x 8192)
// 128x128x16 tile, 256 threads, 8x8 per thread, register prefetch.
// ---------------------------------------------------------------------------
__global__ void k4_gemm() {
    __shared__ float As[16 * 132];
    __shared__ float Bs[16 * 128];
    const int h = blockIdx.z;
    const float* A = d_b + (size_t)h * DNN;
    const float* B = d_v + (size_t)h * DN * DCOL;
    float* C = d_o + (size_t)h * DN * DCOL;
    const int bm0 = blockIdx.y * 128;
    const int bn0 = blockIdx.x * 128;
    const int tid = threadIdx.x;
    const int ar = tid >> 2, ac = (tid & 3) << 2;
    const int br = tid >> 5, bc = (tid & 31) << 2;
    const int ty = tid >> 4, tx = tid & 15;

    float acc[8][8];
    #pragma unroll
    for (int i = 0; i < 8; i++)
        #pragma unroll
        for (int j = 0; j < 8; j++) acc[i][j] = 0.f;

    float4 pa0 = *(const float4*)&A[(size_t)(bm0 + ar) * DN + ac];
    float4 pa1 = *(const float4*)&A[(size_t)(bm0 + ar + 64) * DN + ac];
    float4 pb0 = *(const float4*)&B[(size_t)br * DCOL + bn0 + bc];
    float4 pb1 = *(const float4*)&B[(size_t)(br + 8) * DCOL + bn0 + bc];

    for (int k0 = 0; k0 < DN; k0 += 16) {
        As[(ac + 0) * 132 + ar] = pa0.x;
        As[(ac + 1) * 132 + ar] = pa0.y;
        As[(ac + 2) * 132 + ar] = pa0.z;
        As[(ac + 3) * 132 + ar] = pa0.w;
        As[(ac + 0) * 132 + ar + 64] = pa1.x;
        As[(ac + 1) * 132 + ar + 64] = pa1.y;
        As[(ac + 2) * 132 + ar + 64] = pa1.z;
        As[(ac + 3) * 132 + ar + 64] = pa1.w;
        *(float4*)&Bs[br * 128 + bc] = pb0;
        *(float4*)&Bs[(br + 8) * 128 + bc] = pb1;
        __syncthreads();

        int kn = k0 + 16;
        if (kn < DN) {
            pa0 = *(const float4*)&A[(size_t)(bm0 + ar) * DN + kn + ac];
            pa1 = *(const float4*)&A[(size_t)(bm0 + ar + 64) * DN + kn + ac];
            pb0 = *(const float4*)&B[(size_t)(kn + br) * DCOL + bn0 + bc];
            pb1 = *(const float4*)&B[(size_t)(kn + br + 8) * DCOL + bn0 + bc];
        }

        #pragma unroll
        for (int k = 0; k < 16; k++) {
            float a[8], b[8];
            *(float4*)&a[0] = *(const float4*)&As[k * 132 + ty * 8];
            *(float4*)&a[4] = *(const float4*)&As[k * 132 + ty * 8 + 4];
            *(float4*)&b[0] = *(const float4*)&Bs[k * 128 + tx * 8];
            *(float4*)&b[4] = *(const float4*)&Bs[k * 128 + tx * 8 + 4];
            #pragma unroll
            for (int i = 0; i < 8; i++)
                #pragma unroll
                for (int j = 0; j < 8; j++)
                    acc[i][j] += a[i] * b[j];
        }
        __syncthreads();
    }

    #pragma unroll
    for (int i = 0; i < 8; i++) {
        size_t crow = (size_t)(bm0 + ty * 8 + i) * DCOL + bn0 + tx * 8;
        *(float4*)&C[crow]     = make_float4(acc[i][0], acc[i][1], acc[i][2], acc[i][3]);
        *(float4*)&C[crow + 4] = make_float4(acc[i][4], acc[i][5], acc[i][6], acc[i][7]);
    }
}

// ---------------------------------------------------------------------------
// K5: out[s,i,k] = sum_c (g[s,i,c] * o[h(c)][i][s][d(c)]) * Wo[k][c]
// ---------------------------------------------------------------------------
constexpr int K5_STRIDE = 72;
constexpr int K5_SMEM = (256 * K5_STRIDE * 2) * 4;

__global__ void k5_out(const float* __restrict__ Wo, float* __restrict__ out) {
    extern __shared__ float sm5[];
    float* tsT = sm5;                    // [256][72]: tsT[c][r]
    float* WoT = sm5 + 256 * K5_STRIDE;  // [256][72]: WoT[c][k]

    const int tid = threadIdx.x;
    const int gr0 = blockIdx.x * 64;
    const int ss = gr0 / DN;
    const int i0 = gr0 % DN;   // block never straddles s (768 % 64 == 0)

    for (int t = 0; t < 64; t++) {
        int idx = tid + t * 256;          // 0..16383
        int k = idx >> 8, c = idx & 255;
        WoT[c * K5_STRIDE + k] = Wo[idx]; // Wo row-major [64][256]
    }
    for (int t = 0; t < 64; t++) {
        int idx = tid + t * 256;          // 0..16383
        int r = idx >> 8, c = idx & 255;
        int h = c >> 5, d = c & 31;
        float ov = d_o[((size_t)(h * DN + i0 + r) * DS + ss) * DCH + d];
        float gv = d_g[(size_t)(gr0 + r) * DHC + c];
        tsT[c * K5_STRIDE + r] = gv * ov;
    }
    __syncthreads();

    const int ty = tid >> 4, tx = tid & 15;
    float acc[4][4];
    #pragma unroll
    for (int i = 0; i < 4; i++)
        #pragma unroll
        for (int j = 0; j < 4; j++) acc[i][j] = 0.f;

    #pragma unroll 4
    for (int c = 0; c < 256; c++) {
        float4 a4 = *(const float4*)&tsT[c * K5_STRIDE + ty * 4];
        float4 b4 = *(const float4*)&WoT[c * K5_STRIDE + tx * 4];
        float a[4] = {a4.x, a4.y, a4.z, a4.w};
        float b[4] = {b4.x, b4.y, b4.z, b4.w};
        #pragma unroll
        for (int i = 0; i < 4; i++)
            #pragma unroll
            for (int j = 0; j < 4; j++)
                acc[i][j] += a[i] * b[j];
    }

    #pragma unroll
    for (int i = 0; i < 4; i++) {
        *(float4*)&out[(size_t)(gr0 + ty * 4 + i) * DCM + tx * 4] =
            make_float4(acc[i][0], acc[i][1], acc[i][2], acc[i][3]);
    }
}

// ---------------------------------------------------------------------------
extern "C" void kernel_launch(void* const* d_in, const int* in_sizes, int n_in,
                              void* d_out, int out_size) {
    const float* m    = (const float*)d_in[0];
    const float* z    = (const float*)d_in[1];
    const int*   mask = (const int*)d_in[2];
    const float* nmw  = (const float*)d_in[3];
    const float* nmb  = (const float*)d_in[4];
    const float* nzw  = (const float*)d_in[5];
    const float* nzb  = (const float*)d_in[6];
    const float* Wm   = (const float*)d_in[7];
    const float* Wg   = (const float*)d_in[8];
    const float* Wz   = (const float*)d_in[9];
    const float* Wo   = (const float*)d_in[10];
    float* out = (float*)d_out;

    cudaFuncSetAttribute(k1_ln_vg, cudaFuncAttributeMaxDynamicSharedMemorySize, K1_SMEM);
    cudaFuncSetAttribute(k5_out,   cudaFuncAttributeMaxDynamicSharedMemorySize, K5_SMEM);

    k1_ln_vg<<<DSN / 64, 256, K1_SMEM>>>(m, nmw, nmb, Wm, Wg);
    k2_ln_bias<<<DNN / 8, 256>>>(z, mask, nzw, nzb, Wz);
    k3_softmax<<<DH * DN, 256>>>();
    dim3 g4(DCOL / 128, DN / 128, DH);
    k4_gemm<<<g4, 256>>>();
    k5_out<<<DSN / 64, 256, K5_SMEM>>>(Wo, out);
}

// round 3
// speedup vs baseline: 1.6482x; 1.6482x over previous
#include <cuda_runtime.h>
#include <math.h>
#include <stdint.h>

// Dims
constexpr int DS  = 256;   // S
constexpr int DN  = 768;   // N
constexpr int DCM = 64;    // CM
constexpr int DCZ = 128;   // CZ
constexpr int DH  = 8;     // heads
constexpr int DCH = 32;    // per-head channels
constexpr int DHC = 256;   // H*CH
constexpr int DSN = DS * DN;          // 196608 rows of m
constexpr int DNN = DN * DN;          // 589824 pairs
constexpr int DCOL = DS * DCH;        // 8192 GEMM cols

// Scratch (device globals; no allocations allowed)
__device__ float d_v[DH * DN * DS * DCH];   // [h][j][s][d]
__device__ float d_g[DSN * DHC];            // [s*N+j][hc]
__device__ float d_b[DH * DN * DN];         // [h][i][j]  (logits -> softmax in place)
__device__ float d_o[DH * DN * DS * DCH];   // [h][i][s][d]

__device__ __forceinline__ float to_tf32(float x) {
    uint32_t u;
    asm("cvt.rna.tf32.f32 %0, %1;" : "=r"(u) : "f"(x));
    return __uint_as_float(u);
}

// ---------------------------------------------------------------------------
// K1: LN(m) -> v = mln @ Wm^T (scattered to [h][j][s][d]), g = sigmoid(mln @ Wg^T)
// ---------------------------------------------------------------------------
constexpr int K1_WT_STRIDE = 516;
constexpr int K1_SMEM = (64 * K1_WT_STRIDE + 64 * 68 + 64 * 68) * 4;

__global__ void k1_ln_vg(const float* __restrict__ m,
                         const float* __restrict__ nw,
                         const float* __restrict__ nb,
                         const float* __restrict__ Wm,
                         const float* __restrict__ Wg) {
    extern __shared__ float sm1[];
    float* Wt   = sm1;                         // [64][516]
    float* mlnT = sm1 + 64 * K1_WT_STRIDE;     // [64][68]
    float* mraw = mlnT + 64 * 68;              // [64][68]

    const int tid = threadIdx.x;
    const int gr0 = blockIdx.x * 64;

    #pragma unroll
    for (int t = 0; t < 4; t++) {
        int f = tid + t * 256;                 // float4 id 0..1023
        int r = f >> 4;
        int k = (f & 15) << 2;
        float4 v4 = *(const float4*)&m[(size_t)(gr0 + r) * DCM + k];
        *(float4*)&mraw[r * 68 + k] = v4;
    }
    for (int t = 0; t < 128; t++) {
        int idx = tid + t * 256;               // 0..32767
        int o = idx >> 6;                      // 0..511
        int k = idx & 63;
        float val = (o < 256) ? Wm[o * DCM + k] : Wg[(o - 256) * DCM + k];
        Wt[k * K1_WT_STRIDE + o] = val;
    }
    __syncthreads();

    if (tid < 64) {
        float s1 = 0.f, s2 = 0.f;
        #pragma unroll
        for (int k = 0; k < 64; k++) {
            float x = mraw[tid * 68 + k];
            s1 += x; s2 += x * x;
        }
        float mu  = s1 * (1.f / 64.f);
        float var = s2 * (1.f / 64.f) - mu * mu;
        float inv = rsqrtf(var + 1e-5f);
        #pragma unroll
        for (int k = 0; k < 64; k++) {
            float x = mraw[tid * 68 + k];
            mlnT[k * 68 + tid] = (x - mu) * inv * nw[k] + nb[k];
        }
    }
    __syncthreads();

    const int w = tid >> 5;   // warp 0..7 -> rows w*8..w*8+7
    const int l = tid & 31;   // lane -> cols cb*128 + l*4

    float acc[4][8][4];
    #pragma unroll
    for (int cb = 0; cb < 4; cb++)
        #pragma unroll
        for (int i = 0; i < 8; i++)
            #pragma unroll
            for (int j = 0; j < 4; j++) acc[cb][i][j] = 0.f;

    #pragma unroll 4
    for (int k = 0; k < 64; k++) {
        float a[8];
        *(float4*)&a[0] = *(const float4*)&mlnT[k * 68 + w * 8];
        *(float4*)&a[4] = *(const float4*)&mlnT[k * 68 + w * 8 + 4];
        #pragma unroll
        for (int cb = 0; cb < 4; cb++) {
            float4 bv = *(const float4*)&Wt[k * K1_WT_STRIDE + cb * 128 + l * 4];
            float b[4] = {bv.x, bv.y, bv.z, bv.w};
            #pragma unroll
            for (int i = 0; i < 8; i++)
                #pragma unroll
                for (int j = 0; j < 4; j++)
                    acc[cb][i][j] += a[i] * b[j];
        }
    }

    #pragma unroll
    for (int i = 0; i < 8; i++) {
        int rowg = gr0 + w * 8 + i;
        int ss = rowg / DN;
        int jj = rowg % DN;
        #pragma unroll
        for (int cb = 0; cb < 4; cb++) {
            int c = cb * 128 + l * 4;
            if (c < 256) {
                int h = c >> 5, d = c & 31;
                float4 val = make_float4(acc[cb][i][0], acc[cb][i][1],
                                         acc[cb][i][2], acc[cb][i][3]);
                *(float4*)&d_v[((size_t)(h * DN + jj) * DS + ss) * DCH + d] = val;
            } else {
                int cg = c - 256;
                float4 val;
                val.x = 1.f / (1.f + __expf(-acc[cb][i][0]));
                val.y = 1.f / (1.f + __expf(-acc[cb][i][1]));
                val.z = 1.f / (1.f + __expf(-acc[cb][i][2]));
                val.w = 1.f / (1.f + __expf(-acc[cb][i][3]));
                *(float4*)&d_g[(size_t)rowg * DHC + cg] = val;
            }
        }
    }
}

// ---------------------------------------------------------------------------
// K2: LN(z) + b[h][i][j] = dot(zln, Wz[h]) + mask penalty. One warp per pair.
// ---------------------------------------------------------------------------
__global__ void k2_ln_bias(const float* __restrict__ z,
                           const int* __restrict__ mask,
                           const float* __restrict__ nw,
                           const float* __restrict__ nb,
                           const float* __restrict__ Wz) {
    int gwarp = (blockIdx.x * blockDim.x + threadIdx.x) >> 5;
    int l = threadIdx.x & 31;
    if (gwarp >= DNN) return;

    const float* zr = z + (size_t)gwarp * DCZ;
    float4 xv = *(const float4*)&zr[l * 4];
    float s1 = xv.x + xv.y + xv.z + xv.w;
    float s2 = xv.x * xv.x + xv.y * xv.y + xv.z * xv.z + xv.w * xv.w;
    #pragma unroll
    for (int off = 16; off; off >>= 1) {
        s1 += __shfl_xor_sync(0xffffffffu, s1, off);
        s2 += __shfl_xor_sync(0xffffffffu, s2, off);
    }
    float mu = s1 * (1.f / 128.f);
    float inv = rsqrtf(s2 * (1.f / 128.f) - mu * mu + 1e-5f);
    float4 wv = *(const float4*)&nw[l * 4];
    float4 bv = *(const float4*)&nb[l * 4];
    float xn0 = (xv.x - mu) * inv * wv.x + bv.x;
    float xn1 = (xv.y - mu) * inv * wv.y + bv.y;
    float xn2 = (xv.z - mu) * inv * wv.z + bv.z;
    float xn3 = (xv.w - mu) * inv * wv.w + bv.w;

    float myb = 0.f;
    #pragma unroll
    for (int h = 0; h < DH; h++) {
        float4 w4 = *(const float4*)&Wz[h * DCZ + l * 4];
        float p = xn0 * w4.x + xn1 * w4.y + xn2 * w4.z + xn3 * w4.w;
        #pragma unroll
        for (int off = 16; off; off >>= 1)
            p += __shfl_xor_sync(0xffffffffu, p, off);
        if (l == h) myb = p;
    }
    if (l < DH) {
        float pen = (mask[gwarp] != 0) ? 0.f : -1e6f;
        d_b[(size_t)l * DNN + gwarp] = myb + pen;
    }
}

// ---------------------------------------------------------------------------
// K3: softmax over j (768) per (h,i) row. In place on d_b.
// ---------------------------------------------------------------------------
__global__ void k3_softmax() {
    __shared__ float sd[256];
    float* p = d_b + (size_t)blockIdx.x * DN;
    int tid = threadIdx.x;
    float x0 = p[tid], x1 = p[tid + 256], x2 = p[tid + 512];
    float mx = fmaxf(x0, fmaxf(x1, x2));
    sd[tid] = mx; __syncthreads();
    #pragma unroll
    for (int s = 128; s; s >>= 1) {
        if (tid < s) sd[tid] = fmaxf(sd[tid], sd[tid + s]);
        __syncthreads();
    }
    float bm = sd[0]; __syncthreads();
    float e0 = __expf(x0 - bm), e1 = __expf(x1 - bm), e2 = __expf(x2 - bm);
    sd[tid] = e0 + e1 + e2; __syncthreads();
    #pragma unroll
    for (int s = 128; s; s >>= 1) {
        if (tid < s) sd[tid] += sd[tid + s];
        __syncthreads();
    }
    float invs = 1.f / sd[0];
    p[tid] = e0 * invs; p[tid + 256] = e1 * invs; p[tid + 512] = e2 * invs;
}

// ---------------------------------------------------------------------------
// K4: per-head GEMM on tensor cores (tf32 mma.sync).
// C[h](768 x 8192) = W[h](768 x 768) @ V[h](768 x 8192)
// Block 128x128xK16, 8 warps (2x4), warp tile 64x32 (4x4 mmas of m16n8k8).
// smem stride 136 words -> conflict-free fragment loads.
// ---------------------------------------------------------------------------
constexpr int K4S = 136;

__global__ void k4_gemm_tf32() {
    __shared__ float As[16 * K4S];   // [k][m]
    __shared__ float Bs[16 * K4S];   // [k][n]
    const int h = blockIdx.z;
    const float* A = d_b + (size_t)h * DNN;
    const float* B = d_v + (size_t)h * DN * DCOL;
    float* C = d_o + (size_t)h * DN * DCOL;
    const int bm0 = blockIdx.y * 128;
    const int bn0 = blockIdx.x * 128;
    const int tid = threadIdx.x;
    const int lane = tid & 31;
    const int wid = tid >> 5;
    const int warp_m = wid >> 2;       // 0..1
    const int warp_n = wid & 3;        // 0..3
    const int gid = lane >> 2;         // 0..7
    const int tq  = lane & 3;          // 0..3

    const int ar = tid >> 2, ac = (tid & 3) << 2;   // A tile: rows {ar, ar+64}, k cols ac..ac+3
    const int br = tid >> 5, bc = (tid & 31) << 2;  // B tile: k rows {br, br+8}, cols bc..bc+3

    float acc[4][4][4];
    #pragma unroll
    for (int i = 0; i < 4; i++)
        #pragma unroll
        for (int j = 0; j < 4; j++)
            #pragma unroll
            for (int r = 0; r < 4; r++) acc[i][j][r] = 0.f;

    float4 pa0 = *(const float4*)&A[(size_t)(bm0 + ar) * DN + ac];
    float4 pa1 = *(const float4*)&A[(size_t)(bm0 + ar + 64) * DN + ac];
    float4 pb0 = *(const float4*)&B[(size_t)br * DCOL + bn0 + bc];
    float4 pb1 = *(const float4*)&B[(size_t)(br + 8) * DCOL + bn0 + bc];

    for (int k0 = 0; k0 < DN; k0 += 16) {
        // stage A (transposed to [k][m]) and B ([k][n]) with tf32 conversion
        As[(ac + 0) * K4S + ar] = to_tf32(pa0.x);
        As[(ac + 1) * K4S + ar] = to_tf32(pa0.y);
        As[(ac + 2) * K4S + ar] = to_tf32(pa0.z);
        As[(ac + 3) * K4S + ar] = to_tf32(pa0.w);
        As[(ac + 0) * K4S + ar + 64] = to_tf32(pa1.x);
        As[(ac + 1) * K4S + ar + 64] = to_tf32(pa1.y);
        As[(ac + 2) * K4S + ar + 64] = to_tf32(pa1.z);
        As[(ac + 3) * K4S + ar + 64] = to_tf32(pa1.w);
        float4 qb0 = make_float4(to_tf32(pb0.x), to_tf32(pb0.y), to_tf32(pb0.z), to_tf32(pb0.w));
        float4 qb1 = make_float4(to_tf32(pb1.x), to_tf32(pb1.y), to_tf32(pb1.z), to_tf32(pb1.w));
        *(float4*)&Bs[br * K4S + bc] = qb0;
        *(float4*)&Bs[(br + 8) * K4S + bc] = qb1;
        __syncthreads();

        int kn = k0 + 16;
        if (kn < DN) {
            pa0 = *(const float4*)&A[(size_t)(bm0 + ar) * DN + kn + ac];
            pa1 = *(const float4*)&A[(size_t)(bm0 + ar + 64) * DN + kn + ac];
            pb0 = *(const float4*)&B[(size_t)(kn + br) * DCOL + bn0 + bc];
            pb1 = *(const float4*)&B[(size_t)(kn + br + 8) * DCOL + bn0 + bc];
        }

        #pragma unroll
        for (int s = 0; s < 2; s++) {
            uint32_t af[4][4], bf[4][2];
            const int a_base0 = (s * 8 + tq) * K4S + warp_m * 64 + gid;
            const int a_base1 = a_base0 + 4 * K4S;
            const int b_base0 = (s * 8 + tq) * K4S + warp_n * 32 + gid;
            const int b_base1 = b_base0 + 4 * K4S;
            #pragma unroll
            for (int mt = 0; mt < 4; mt++) {
                af[mt][0] = __float_as_uint(As[a_base0 + mt * 16]);
                af[mt][1] = __float_as_uint(As[a_base0 + mt * 16 + 8]);
                af[mt][2] = __float_as_uint(As[a_base1 + mt * 16]);
                af[mt][3] = __float_as_uint(As[a_base1 + mt * 16 + 8]);
            }
            #pragma unroll
            for (int nt = 0; nt < 4; nt++) {
                bf[nt][0] = __float_as_uint(Bs[b_base0 + nt * 8]);
                bf[nt][1] = __float_as_uint(Bs[b_base1 + nt * 8]);
            }
            #pragma unroll
            for (int mt = 0; mt < 4; mt++)
                #pragma unroll
                for (int nt = 0; nt < 4; nt++) {
                    asm volatile(
                        "mma.sync.aligned.m16n8k8.row.col.f32.tf32.tf32.f32 "
                        "{%0,%1,%2,%3}, {%4,%5,%6,%7}, {%8,%9}, {%0,%1,%2,%3};"
                        : "+f"(acc[mt][nt][0]), "+f"(acc[mt][nt][1]),
                          "+f"(acc[mt][nt][2]), "+f"(acc[mt][nt][3])
                        : "r"(af[mt][0]), "r"(af[mt][1]), "r"(af[mt][2]), "r"(af[mt][3]),
                          "r"(bf[nt][0]), "r"(bf[nt][1]));
                }
        }
        __syncthreads();
    }

    #pragma unroll
    for (int mt = 0; mt < 4; mt++) {
        #pragma unroll
        for (int nt = 0; nt < 4; nt++) {
            int row = bm0 + warp_m * 64 + mt * 16 + gid;
            int col = bn0 + warp_n * 32 + nt * 8 + tq * 2;
            *(float2*)&C[(size_t)row * DCOL + col] =
                make_float2(acc[mt][nt][0], acc[mt][nt][1]);
            *(float2*)&C[(size_t)(row + 8) * DCOL + col] =
                make_float2(acc[mt][nt][2], acc[mt][nt][3]);
        }
    }
}

// ---------------------------------------------------------------------------
// K5: out[s,i,k] = sum_c (g[s,i,c] * o[h(c)][i][s][d(c)]) * Wo[k][c]
// ---------------------------------------------------------------------------
constexpr int K5_STRIDE = 72;
constexpr int K5_SMEM = (256 * K5_STRIDE * 2) * 4;

__global__ void k5_out(const float* __restrict__ Wo, float* __restrict__ out) {
    extern __shared__ float sm5[];
    float* tsT = sm5;                    // [256][72]: tsT[c][r]
    float* WoT = sm5 + 256 * K5_STRIDE;  // [256][72]: WoT[c][k]

    const int tid = threadIdx.x;
    const int gr0 = blockIdx.x * 64;
    const int ss = gr0 / DN;
    const int i0 = gr0 % DN;   // block never straddles s (768 % 64 == 0)

    for (int t = 0; t < 64; t++) {
        int idx = tid + t * 256;          // 0..16383
        int k = idx >> 8, c = idx & 255;
        WoT[c * K5_STRIDE + k] = Wo[idx]; // Wo row-major [64][256]
    }
    for (int t = 0; t < 64; t++) {
        int idx = tid + t * 256;          // 0..16383
        int r = idx >> 8, c = idx & 255;
        int h = c >> 5, d = c & 31;
        float ov = d_o[((size_t)(h * DN + i0 + r) * DS + ss) * DCH + d];
        float gv = d_g[(size_t)(gr0 + r) * DHC + c];
        tsT[c * K5_STRIDE + r] = gv * ov;
    }
    __syncthreads();

    const int ty = tid >> 4, tx = tid & 15;
    float acc[4][4];
    #pragma unroll
    for (int i = 0; i < 4; i++)
        #pragma unroll
        for (int j = 0; j < 4; j++) acc[i][j] = 0.f;

    #pragma unroll 4
    for (int c = 0; c < 256; c++) {
        float4 a4 = *(const float4*)&tsT[c * K5_STRIDE + ty * 4];
        float4 b4 = *(const float4*)&WoT[c * K5_STRIDE + tx * 4];
        float a[4] = {a4.x, a4.y, a4.z, a4.w};
        float b[4] = {b4.x, b4.y, b4.z, b4.w};
        #pragma unroll
        for (int i = 0; i < 4; i++)
            #pragma unroll
            for (int j = 0; j < 4; j++)
                acc[i][j] += a[i] * b[j];
    }

    #pragma unroll
    for (int i = 0; i < 4; i++) {
        *(float4*)&out[(size_t)(gr0 + ty * 4 + i) * DCM + tx * 4] =
            make_float4(acc[i][0], acc[i][1], acc[i][2], acc[i][3]);
    }
}

// ---------------------------------------------------------------------------
extern "C" void kernel_launch(void* const* d_in, const int* in_sizes, int n_in,
                              void* d_out, int out_size) {
    const float* m    = (const float*)d_in[0];
    const float* z    = (const float*)d_in[1];
    const int*   mask = (const int*)d_in[2];
    const float* nmw  = (const float*)d_in[3];
    const float* nmb  = (const float*)d_in[4];
    const float* nzw  = (const float*)d_in[5];
    const float* nzb  = (const float*)d_in[6];
    const float* Wm   = (const float*)d_in[7];
    const float* Wg   = (const float*)d_in[8];
    const float* Wz   = (const float*)d_in[9];
    const float* Wo   = (const float*)d_in[10];
    float* out = (float*)d_out;

    cudaFuncSetAttribute(k1_ln_vg, cudaFuncAttributeMaxDynamicSharedMemorySize, K1_SMEM);
    cudaFuncSetAttribute(k5_out,   cudaFuncAttributeMaxDynamicSharedMemorySize, K5_SMEM);

    k1_ln_vg<<<DSN / 64, 256, K1_SMEM>>>(m, nmw, nmb, Wm, Wg);
    k2_ln_bias<<<DNN / 8, 256>>>(z, mask, nzw, nzb, Wz);
    k3_softmax<<<DH * DN, 256>>>();
    dim3 g4(DCOL / 128, DN / 128, DH);
    k4_gemm_tf32<<<g4, 256>>>();
    k5_out<<<DSN / 64, 256, K5_SMEM>>>(Wo, out);
}

// round 4
// speedup vs baseline: 2.5308x; 1.5355x over previous
#include <cuda_runtime.h>
#include <math.h>
#include <stdint.h>

// Dims
constexpr int DS  = 256;   // S
constexpr int DN  = 768;   // N
constexpr int DCM = 64;    // CM
constexpr int DCZ = 128;   // CZ
constexpr int DH  = 8;     // heads
constexpr int DCH = 32;    // per-head channels
constexpr int DHC = 256;   // H*CH
constexpr int DSN = DS * DN;          // 196608 rows of m
constexpr int DNN = DN * DN;          // 589824 pairs
constexpr int DCOL = DS * DCH;        // 8192 GEMM cols

// Scratch (device globals; no allocations allowed)
__device__ float d_v[DH * DN * DS * DCH];   // [h][j][s][d]
__device__ float d_g[DSN * DHC];            // [s*N+j][hc]
__device__ float d_b[DH * DN * DN];         // [h][i][j]  (logits -> softmax in place)
__device__ float d_o[DH * DN * DS * DCH];   // [h][i][s][d]

__device__ __forceinline__ float to_tf32(float x) {
    uint32_t u;
    asm("cvt.rna.tf32.f32 %0, %1;" : "=r"(u) : "f"(x));
    return __uint_as_float(u);
}

#define MMA_TF32(acc, af, bf)                                                 \
    asm volatile(                                                             \
        "mma.sync.aligned.m16n8k8.row.col.f32.tf32.tf32.f32 "                 \
        "{%0,%1,%2,%3}, {%4,%5,%6,%7}, {%8,%9}, {%0,%1,%2,%3};"               \
        : "+f"((acc)[0]), "+f"((acc)[1]), "+f"((acc)[2]), "+f"((acc)[3])      \
        : "r"((af)[0]), "r"((af)[1]), "r"((af)[2]), "r"((af)[3]),             \
          "r"((bf)[0]), "r"((bf)[1]))

// ---------------------------------------------------------------------------
// K1 (tensor): LN(m) then [128 x 64] @ [64 x 128] per block via tf32 mma.
// grid = (1536, 4); blockIdx.y picks 128 of the 512 fused output cols
// (cols 0-255 = v via Wm, 256-511 = g via Wg).
// smem: As[128][68] row-major (LN'd, tf32), Bs[64][136] = W^T tile (tf32).
// ---------------------------------------------------------------------------
constexpr int K1A = 68;
constexpr int K1B = 136;
constexpr int K1_SMEM = (128 * K1A + 64 * K1B + 64 + 64) * 4;

__global__ void k1_ln_vg_tc(const float* __restrict__ m,
                            const float* __restrict__ nw,
                            const float* __restrict__ nb,
                            const float* __restrict__ Wm,
                            const float* __restrict__ Wg) {
    extern __shared__ float sm1[];
    float* As  = sm1;                    // [128][68]
    float* Bs  = As + 128 * K1A;         // [64][136]
    float* snw = Bs + 64 * K1B;          // [64]
    float* snb = snw + 64;               // [64]

    const int tid = threadIdx.x;
    const int gr0 = blockIdx.x * 128;
    const int bn0 = blockIdx.y * 128;    // global output col base

    // load m tile [128][64] row-major into As (raw)
    #pragma unroll
    for (int t = 0; t < 8; t++) {
        int f = tid + t * 256;           // float4 id 0..2047
        int r = f >> 4;
        int k = (f & 15) << 2;
        float4 v4 = *(const float4*)&m[(size_t)(gr0 + r) * DCM + k];
        *(float4*)&As[r * K1A + k] = v4;
    }
    // load W tile transposed: Bs[k][n] (tf32)
    const float* Wsrc = (bn0 < 256) ? (Wm + (size_t)bn0 * DCM)
                                    : (Wg + (size_t)(bn0 - 256) * DCM);
    #pragma unroll
    for (int t = 0; t < 32; t++) {
        int idx = tid + t * 256;         // 0..8191
        int n = idx >> 6;                // 0..127
        int k = idx & 63;
        Bs[k * K1B + n] = to_tf32(Wsrc[n * DCM + k]);
    }
    if (tid < 64) { snw[tid] = nw[tid]; snb[tid] = nb[tid]; }
    __syncthreads();

    // LayerNorm in place (tf32-converted), one thread per row
    if (tid < 128) {
        float s1 = 0.f, s2 = 0.f;
        #pragma unroll
        for (int k = 0; k < 64; k++) {
            float x = As[tid * K1A + k];
            s1 += x; s2 += x * x;
        }
        float mu  = s1 * (1.f / 64.f);
        float var = s2 * (1.f / 64.f) - mu * mu;
        float inv = rsqrtf(var + 1e-5f);
        #pragma unroll
        for (int k = 0; k < 64; k++) {
            float x = As[tid * K1A + k];
            As[tid * K1A + k] = to_tf32((x - mu) * inv * snw[k] + snb[k]);
        }
    }
    __syncthreads();

    const int lane = tid & 31;
    const int wid  = tid >> 5;
    const int warp_m = wid >> 2;         // 0..1 -> 64 rows
    const int warp_n = wid & 3;          // 0..3 -> 32 cols
    const int gid = lane >> 2;
    const int tq  = lane & 3;

    float acc[4][4][4];
    #pragma unroll
    for (int i = 0; i < 4; i++)
        #pragma unroll
        for (int j = 0; j < 4; j++)
            #pragma unroll
            for (int r = 0; r < 4; r++) acc[i][j][r] = 0.f;

    #pragma unroll
    for (int k8 = 0; k8 < 8; k8++) {
        uint32_t af[4][4], bf[4][2];
        #pragma unroll
        for (int mt = 0; mt < 4; mt++) {
            int row = warp_m * 64 + mt * 16 + gid;
            af[mt][0] = __float_as_uint(As[row * K1A + k8 * 8 + tq]);
            af[mt][1] = __float_as_uint(As[(row + 8) * K1A + k8 * 8 + tq]);
            af[mt][2] = __float_as_uint(As[row * K1A + k8 * 8 + tq + 4]);
            af[mt][3] = __float_as_uint(As[(row + 8) * K1A + k8 * 8 + tq + 4]);
        }
        #pragma unroll
        for (int nt = 0; nt < 4; nt++) {
            int col = warp_n * 32 + nt * 8 + gid;
            bf[nt][0] = __float_as_uint(Bs[(k8 * 8 + tq) * K1B + col]);
            bf[nt][1] = __float_as_uint(Bs[(k8 * 8 + tq + 4) * K1B + col]);
        }
        #pragma unroll
        for (int mt = 0; mt < 4; mt++)
            #pragma unroll
            for (int nt = 0; nt < 4; nt++)
                MMA_TF32(acc[mt][nt], af[mt], bf[nt]);
    }

    // epilogue: scatter v / sigmoid g
    #pragma unroll
    for (int mt = 0; mt < 4; mt++) {
        #pragma unroll
        for (int half = 0; half < 2; half++) {
            int rowg = gr0 + warp_m * 64 + mt * 16 + gid + half * 8;
            int ss = rowg / DN;
            int jj = rowg - ss * DN;
            #pragma unroll
            for (int nt = 0; nt < 4; nt++) {
                int cglob = bn0 + warp_n * 32 + nt * 8 + tq * 2;
                float c0 = acc[mt][nt][half * 2];
                float c1 = acc[mt][nt][half * 2 + 1];
                if (cglob < 256) {
                    int h = cglob >> 5, d = cglob & 31;
                    *(float2*)&d_v[((size_t)(h * DN + jj) * DS + ss) * DCH + d] =
                        make_float2(c0, c1);
                } else {
                    int cg = cglob - 256;
                    float g0 = 1.f / (1.f + __expf(-c0));
                    float g1 = 1.f / (1.f + __expf(-c1));
                    *(float2*)&d_g[(size_t)rowg * DHC + cg] = make_float2(g0, g1);
                }
            }
        }
    }
}

// ---------------------------------------------------------------------------
// K2: LN(z) + b[h][i][j] = dot(zln, Wz[h]) + mask penalty. One warp per pair.
// ---------------------------------------------------------------------------
__global__ void k2_ln_bias(const float* __restrict__ z,
                           const int* __restrict__ mask,
                           const float* __restrict__ nw,
                           const float* __restrict__ nb,
                           const float* __restrict__ Wz) {
    int gwarp = (blockIdx.x * blockDim.x + threadIdx.x) >> 5;
    int l = threadIdx.x & 31;
    if (gwarp >= DNN) return;

    const float* zr = z + (size_t)gwarp * DCZ;
    float4 xv = *(const float4*)&zr[l * 4];
    float s1 = xv.x + xv.y + xv.z + xv.w;
    float s2 = xv.x * xv.x + xv.y * xv.y + xv.z * xv.z + xv.w * xv.w;
    #pragma unroll
    for (int off = 16; off; off >>= 1) {
        s1 += __shfl_xor_sync(0xffffffffu, s1, off);
        s2 += __shfl_xor_sync(0xffffffffu, s2, off);
    }
    float mu = s1 * (1.f / 128.f);
    float inv = rsqrtf(s2 * (1.f / 128.f) - mu * mu + 1e-5f);
    float4 wv = *(const float4*)&nw[l * 4];
    float4 bv = *(const float4*)&nb[l * 4];
    float xn0 = (xv.x - mu) * inv * wv.x + bv.x;
    float xn1 = (xv.y - mu) * inv * wv.y + bv.y;
    float xn2 = (xv.z - mu) * inv * wv.z + bv.z;
    float xn3 = (xv.w - mu) * inv * wv.w + bv.w;

    float myb = 0.f;
    #pragma unroll
    for (int h = 0; h < DH; h++) {
        float4 w4 = *(const float4*)&Wz[h * DCZ + l * 4];
        float p = xn0 * w4.x + xn1 * w4.y + xn2 * w4.z + xn3 * w4.w;
        #pragma unroll
        for (int off = 16; off; off >>= 1)
            p += __shfl_xor_sync(0xffffffffu, p, off);
        if (l == h) myb = p;
    }
    if (l < DH) {
        float pen = (mask[gwarp] != 0) ? 0.f : -1e6f;
        d_b[(size_t)l * DNN + gwarp] = myb + pen;
    }
}

// ---------------------------------------------------------------------------
// K3: softmax over j (768) per (h,i) row. In place on d_b.
// ---------------------------------------------------------------------------
__global__ void k3_softmax() {
    __shared__ float sd[256];
    float* p = d_b + (size_t)blockIdx.x * DN;
    int tid = threadIdx.x;
    float x0 = p[tid], x1 = p[tid + 256], x2 = p[tid + 512];
    float mx = fmaxf(x0, fmaxf(x1, x2));
    sd[tid] = mx; __syncthreads();
    #pragma unroll
    for (int s = 128; s; s >>= 1) {
        if (tid < s) sd[tid] = fmaxf(sd[tid], sd[tid + s]);
        __syncthreads();
    }
    float bm = sd[0]; __syncthreads();
    float e0 = __expf(x0 - bm), e1 = __expf(x1 - bm), e2 = __expf(x2 - bm);
    sd[tid] = e0 + e1 + e2; __syncthreads();
    #pragma unroll
    for (int s = 128; s; s >>= 1) {
        if (tid < s) sd[tid] += sd[tid + s];
        __syncthreads();
    }
    float invs = 1.f / sd[0];
    p[tid] = e0 * invs; p[tid + 256] = e1 * invs; p[tid + 512] = e2 * invs;
}

// ---------------------------------------------------------------------------
// K4: per-head GEMM on tensor cores (tf32 mma.sync). Unchanged from R2.
// ---------------------------------------------------------------------------
constexpr int K4S = 136;

__global__ void k4_gemm_tf32() {
    __shared__ float As[16 * K4S];   // [k][m]
    __shared__ float Bs[16 * K4S];   // [k][n]
    const int h = blockIdx.z;
    const float* A = d_b + (size_t)h * DNN;
    const float* B = d_v + (size_t)h * DN * DCOL;
    float* C = d_o + (size_t)h * DN * DCOL;
    const int bm0 = blockIdx.y * 128;
    const int bn0 = blockIdx.x * 128;
    const int tid = threadIdx.x;
    const int lane = tid & 31;
    const int wid = tid >> 5;
    const int warp_m = wid >> 2;       // 0..1
    const int warp_n = wid & 3;        // 0..3
    const int gid = lane >> 2;         // 0..7
    const int tq  = lane & 3;          // 0..3

    const int ar = tid >> 2, ac = (tid & 3) << 2;
    const int br = tid >> 5, bc = (tid & 31) << 2;

    float acc[4][4][4];
    #pragma unroll
    for (int i = 0; i < 4; i++)
        #pragma unroll
        for (int j = 0; j < 4; j++)
            #pragma unroll
            for (int r = 0; r < 4; r++) acc[i][j][r] = 0.f;

    float4 pa0 = *(const float4*)&A[(size_t)(bm0 + ar) * DN + ac];
    float4 pa1 = *(const float4*)&A[(size_t)(bm0 + ar + 64) * DN + ac];
    float4 pb0 = *(const float4*)&B[(size_t)br * DCOL + bn0 + bc];
    float4 pb1 = *(const float4*)&B[(size_t)(br + 8) * DCOL + bn0 + bc];

    for (int k0 = 0; k0 < DN; k0 += 16) {
        As[(ac + 0) * K4S + ar] = to_tf32(pa0.x);
        As[(ac + 1) * K4S + ar] = to_tf32(pa0.y);
        As[(ac + 2) * K4S + ar] = to_tf32(pa0.z);
        As[(ac + 3) * K4S + ar] = to_tf32(pa0.w);
        As[(ac + 0) * K4S + ar + 64] = to_tf32(pa1.x);
        As[(ac + 1) * K4S + ar + 64] = to_tf32(pa1.y);
        As[(ac + 2) * K4S + ar + 64] = to_tf32(pa1.z);
        As[(ac + 3) * K4S + ar + 64] = to_tf32(pa1.w);
        float4 qb0 = make_float4(to_tf32(pb0.x), to_tf32(pb0.y), to_tf32(pb0.z), to_tf32(pb0.w));
        float4 qb1 = make_float4(to_tf32(pb1.x), to_tf32(pb1.y), to_tf32(pb1.z), to_tf32(pb1.w));
        *(float4*)&Bs[br * K4S + bc] = qb0;
        *(float4*)&Bs[(br + 8) * K4S + bc] = qb1;
        __syncthreads();

        int kn = k0 + 16;
        if (kn < DN) {
            pa0 = *(const float4*)&A[(size_t)(bm0 + ar) * DN + kn + ac];
            pa1 = *(const float4*)&A[(size_t)(bm0 + ar + 64) * DN + kn + ac];
            pb0 = *(const float4*)&B[(size_t)(kn + br) * DCOL + bn0 + bc];
            pb1 = *(const float4*)&B[(size_t)(kn + br + 8) * DCOL + bn0 + bc];
        }

        #pragma unroll
        for (int s = 0; s < 2; s++) {
            uint32_t af[4][4], bf[4][2];
            const int a_base0 = (s * 8 + tq) * K4S + warp_m * 64 + gid;
            const int a_base1 = a_base0 + 4 * K4S;
            const int b_base0 = (s * 8 + tq) * K4S + warp_n * 32 + gid;
            const int b_base1 = b_base0 + 4 * K4S;
            #pragma unroll
            for (int mt = 0; mt < 4; mt++) {
                af[mt][0] = __float_as_uint(As[a_base0 + mt * 16]);
                af[mt][1] = __float_as_uint(As[a_base0 + mt * 16 + 8]);
                af[mt][2] = __float_as_uint(As[a_base1 + mt * 16]);
                af[mt][3] = __float_as_uint(As[a_base1 + mt * 16 + 8]);
            }
            #pragma unroll
            for (int nt = 0; nt < 4; nt++) {
                bf[nt][0] = __float_as_uint(Bs[b_base0 + nt * 8]);
                bf[nt][1] = __float_as_uint(Bs[b_base1 + nt * 8]);
            }
            #pragma unroll
            for (int mt = 0; mt < 4; mt++)
                #pragma unroll
                for (int nt = 0; nt < 4; nt++)
                    MMA_TF32(acc[mt][nt], af[mt], bf[nt]);
        }
        __syncthreads();
    }

    #pragma unroll
    for (int mt = 0; mt < 4; mt++) {
        #pragma unroll
        for (int nt = 0; nt < 4; nt++) {
            int row = bm0 + warp_m * 64 + mt * 16 + gid;
            int col = bn0 + warp_n * 32 + nt * 8 + tq * 2;
            *(float2*)&C[(size_t)row * DCOL + col] =
                make_float2(acc[mt][nt][0], acc[mt][nt][1]);
            *(float2*)&C[(size_t)(row + 8) * DCOL + col] =
                make_float2(acc[mt][nt][2], acc[mt][nt][3]);
        }
    }
}

// ---------------------------------------------------------------------------
// K5 (tensor): out[128 x 64] += (g*o_gather)[128 x 256] @ WoT[256 x 64]
// 4 K-chunks of 64; gather+gate fused into smem A-stage.
// smem: As[128][68], Bs[64][72].
// ---------------------------------------------------------------------------
constexpr int K5A = 68;
constexpr int K5B = 72;
constexpr int K5_SMEM = (128 * K5A + 64 * K5B) * 4;

__global__ void k5_out_tc(const float* __restrict__ Wo, float* __restrict__ out) {
    extern __shared__ float sm5[];
    float* As = sm5;                 // [128][68]
    float* Bs = As + 128 * K5A;      // [64][72]

    const int tid = threadIdx.x;
    const int gr0 = blockIdx.x * 128;
    const int ss = gr0 / DN;
    const int i0 = gr0 - ss * DN;    // 768 % 128 == 0: no straddle

    const int lane = tid & 31;
    const int wid  = tid >> 5;
    const int warp_m = wid >> 1;     // 0..3 -> 32 rows
    const int warp_n = wid & 1;      // 0..1 -> 32 cols
    const int gid = lane >> 2;
    const int tq  = lane & 3;

    float acc[2][4][4];
    #pragma unroll
    for (int i = 0; i < 2; i++)
        #pragma unroll
        for (int j = 0; j < 4; j++)
            #pragma unroll
            for (int r = 0; r < 4; r++) acc[i][j][r] = 0.f;

    for (int ck0 = 0; ck0 < DHC; ck0 += 64) {
        // Bs[k_local][n] = tf32(Wo[n][ck0+k_local])
        #pragma unroll
        for (int t = 0; t < 16; t++) {
            int idx = tid + t * 256;     // 0..4095
            int n = idx >> 6;            // 0..63
            int cl = idx & 63;
            Bs[cl * K5B + n] = to_tf32(Wo[n * DHC + ck0 + cl]);
        }
        // As[r][cl] = tf32( g[row][c] * o_gather )
        #pragma unroll
        for (int t = 0; t < 32; t++) {
            int idx = tid + t * 256;     // 0..8191
            int r = idx >> 6;
            int cl = idx & 63;
            int c = ck0 + cl;
            int h = c >> 5, d = c & 31;
            float ov = d_o[((size_t)(h * DN + i0 + r) * DS + ss) * DCH + d];
            float gv = d_g[(size_t)(gr0 + r) * DHC + c];
            As[r * K5A + cl] = to_tf32(gv * ov);
        }
        __syncthreads();

        #pragma unroll
        for (int k8 = 0; k8 < 8; k8++) {
            uint32_t af[2][4], bf[4][2];
            #pragma unroll
            for (int mt = 0; mt < 2; mt++) {
                int row = warp_m * 32 + mt * 16 + gid;
                af[mt][0] = __float_as_uint(As[row * K5A + k8 * 8 + tq]);
                af[mt][1] = __float_as_uint(As[(row + 8) * K5A + k8 * 8 + tq]);
                af[mt][2] = __float_as_uint(As[row * K5A + k8 * 8 + tq + 4]);
                af[mt][3] = __float_as_uint(As[(row + 8) * K5A + k8 * 8 + tq + 4]);
            }
            #pragma unroll
            for (int nt = 0; nt < 4; nt++) {
                int col = warp_n * 32 + nt * 8 + gid;
                bf[nt][0] = __float_as_uint(Bs[(k8 * 8 + tq) * K5B + col]);
                bf[nt][1] = __float_as_uint(Bs[(k8 * 8 + tq + 4) * K5B + col]);
            }
            #pragma unroll
            for (int mt = 0; mt < 2; mt++)
                #pragma unroll
                for (int nt = 0; nt < 4; nt++)
                    MMA_TF32(acc[mt][nt], af[mt], bf[nt]);
        }
        __syncthreads();
    }

    #pragma unroll
    for (int mt = 0; mt < 2; mt++) {
        #pragma unroll
        for (int nt = 0; nt < 4; nt++) {
            int row = gr0 + warp_m * 32 + mt * 16 + gid;
            int col = warp_n * 32 + nt * 8 + tq * 2;
            *(float2*)&out[(size_t)row * DCM + col] =
                make_float2(acc[mt][nt][0], acc[mt][nt][1]);
            *(float2*)&out[(size_t)(row + 8) * DCM + col] =
                make_float2(acc[mt][nt][2], acc[mt][nt][3]);
        }
    }
}

// ---------------------------------------------------------------------------
extern "C" void kernel_launch(void* const* d_in, const int* in_sizes, int n_in,
                              void* d_out, int out_size) {
    const float* m    = (const float*)d_in[0];
    const float* z    = (const float*)d_in[1];
    const int*   mask = (const int*)d_in[2];
    const float* nmw  = (const float*)d_in[3];
    const float* nmb  = (const float*)d_in[4];
    const float* nzw  = (const float*)d_in[5];
    const float* nzb  = (const float*)d_in[6];
    const float* Wm   = (const float*)d_in[7];
    const float* Wg   = (const float*)d_in[8];
    const float* Wz   = (const float*)d_in[9];
    const float* Wo   = (const float*)d_in[10];
    float* out = (float*)d_out;

    cudaFuncSetAttribute(k1_ln_vg_tc, cudaFuncAttributeMaxDynamicSharedMemorySize, K1_SMEM);
    cudaFuncSetAttribute(k5_out_tc,   cudaFuncAttributeMaxDynamicSharedMemorySize, K5_SMEM);

    dim3 g1(DSN / 128, 4);
    k1_ln_vg_tc<<<g1, 256, K1_SMEM>>>(m, nmw, nmb, Wm, Wg);
    k2_ln_bias<<<DNN / 8, 256>>>(z, mask, nzw, nzb, Wz);
    k3_softmax<<<DH * DN, 256>>>();
    dim3 g4(DCOL / 128, DN / 128, DH);
    k4_gemm_tf32<<<g4, 256>>>();
    k5_out_tc<<<DSN / 128, 256, K5_SMEM>>>(Wo, out);
}